// round 2
// baseline (speedup 1.0000x reference)
#include <cuda_runtime.h>
#include <cuda_bf16.h>
#include <stdint.h>

#define NN 100000
#define EE 1600000
#define DD 128

// ---------------- scratch (static __device__, no allocation) ----------------
__device__ float g_deg[NN];            // deg, then dinv in place
__device__ int   g_cnt[NN];
__device__ int   g_rowptr[NN + 1];
__device__ int   g_fill[NN];
__device__ int   g_col[EE + NN];
__device__ float g_val[EE + NN];
__device__ float g_Z [NN * DD];
__device__ float g_HA[NN * DD];
__device__ float g_HB[NN * DD];
__device__ float g_Z5[NN * 2];

// ---------------- graph preprocessing ----------------
__global__ void init_kernel() {
    int i = blockIdx.x * blockDim.x + threadIdx.x;
    if (i < NN) {
        g_deg[i]  = 1.0f;   // self-loop weight
        g_cnt[i]  = 1;      // self-loop edge
        g_fill[i] = 0;
    }
}

__global__ void deg_cnt_kernel(const int* __restrict__ ei,
                               const float* __restrict__ w) {
    int e = blockIdx.x * blockDim.x + threadIdx.x;
    if (e >= EE) return;
    int d = ei[EE + e];
    atomicAdd(&g_deg[d], w[e]);
    atomicAdd(&g_cnt[d], 1);
}

__global__ void dinv_kernel() {
    int i = blockIdx.x * blockDim.x + threadIdx.x;
    if (i < NN) g_deg[i] = rsqrtf(g_deg[i]);   // deg >= 1 always (self-loop)
}

// single-block exclusive scan of g_cnt -> g_rowptr
__global__ void scan_kernel() {
    __shared__ int s[1024];
    const int t = threadIdx.x;
    const int CH = (NN + 1023) / 1024;
    int beg = t * CH;
    int end = min(beg + CH, NN);
    int sum = 0;
    for (int i = beg; i < end; i++) sum += g_cnt[i];
    s[t] = sum;
    __syncthreads();
    // Hillis-Steele inclusive scan
    for (int off = 1; off < 1024; off <<= 1) {
        int u = 0;
        if (t >= off) u = s[t - off];
        __syncthreads();
        s[t] += u;
        __syncthreads();
    }
    int run = s[t] - sum;   // exclusive base for this thread's chunk
    for (int i = beg; i < end; i++) {
        g_rowptr[i] = run;
        run += g_cnt[i];
    }
    if (t == 1023) g_rowptr[NN] = s[1023];
}

__global__ void csr_fill_kernel(const int* __restrict__ ei,
                                const float* __restrict__ w) {
    int e = blockIdx.x * blockDim.x + threadIdx.x;
    if (e < EE) {
        int s = ei[e];
        int d = ei[EE + e];
        int pos = g_rowptr[d] + atomicAdd(&g_fill[d], 1);
        g_col[pos] = s;
        g_val[pos] = g_deg[s] * w[e] * g_deg[d];    // g_deg holds dinv now
    } else if (e < EE + NN) {
        int i = e - EE;
        int pos = g_rowptr[i] + atomicAdd(&g_fill[i], 1);
        float di = g_deg[i];
        g_col[pos] = i;
        g_val[pos] = di * di;
    }
}

// ---------------- dense GEMM: C[M,128] = A[M,128] @ B[128,128] ----------------
#define BM 128
#define BN 128
#define BK 16
__global__ __launch_bounds__(256) void gemm128_kernel(const float* __restrict__ A,
                                                      const float* __restrict__ B,
                                                      float* __restrict__ C, int M) {
    __shared__ float As[BK * BM];   // As[k][m]  (k-major so fragments are LDS.128)
    __shared__ float Bs[BK * BN];   // Bs[k][n]
    const int tid = threadIdx.x;
    const int tx = tid & 15;        // 16 column groups of 8
    const int ty = tid >> 4;        // 16 row groups of 8
    const int m0 = blockIdx.x * BM;

    float acc[8][8];
#pragma unroll
    for (int i = 0; i < 8; i++)
#pragma unroll
        for (int j = 0; j < 8; j++) acc[i][j] = 0.0f;

    for (int k0 = 0; k0 < 128; k0 += BK) {
        // load A tile (transposed into smem)
#pragma unroll
        for (int r2 = 0; r2 < 2; r2++) {
            int li  = tid + r2 * 256;      // 0..511
            int row = li >> 2;             // 0..127
            int cg  = li & 3;              // which float4 of the 16 k's
            float4 a = make_float4(0.f, 0.f, 0.f, 0.f);
            int grow = m0 + row;
            if (grow < M)
                a = *reinterpret_cast<const float4*>(A + (size_t)grow * DD + k0 + cg * 4);
            As[(cg * 4 + 0) * BM + row] = a.x;
            As[(cg * 4 + 1) * BM + row] = a.y;
            As[(cg * 4 + 2) * BM + row] = a.z;
            As[(cg * 4 + 3) * BM + row] = a.w;
        }
        // load B tile (straight copy)
#pragma unroll
        for (int r2 = 0; r2 < 2; r2++) {
            int li  = tid + r2 * 256;
            int row = li >> 5;             // 0..15
            int cg  = li & 31;             // 32 float4 per row
            *reinterpret_cast<float4*>(Bs + row * BN + cg * 4) =
                *reinterpret_cast<const float4*>(B + (size_t)(k0 + row) * 128 + cg * 4);
        }
        __syncthreads();
#pragma unroll
        for (int kk = 0; kk < BK; kk++) {
            float a[8], b[8];
            *reinterpret_cast<float4*>(&a[0]) = *reinterpret_cast<const float4*>(&As[kk * BM + ty * 8]);
            *reinterpret_cast<float4*>(&a[4]) = *reinterpret_cast<const float4*>(&As[kk * BM + ty * 8 + 4]);
            *reinterpret_cast<float4*>(&b[0]) = *reinterpret_cast<const float4*>(&Bs[kk * BN + tx * 8]);
            *reinterpret_cast<float4*>(&b[4]) = *reinterpret_cast<const float4*>(&Bs[kk * BN + tx * 8 + 4]);
#pragma unroll
            for (int i = 0; i < 8; i++)
#pragma unroll
                for (int j = 0; j < 8; j++)
                    acc[i][j] = fmaf(a[i], b[j], acc[i][j]);
        }
        __syncthreads();
    }
#pragma unroll
    for (int i = 0; i < 8; i++) {
        int grow = m0 + ty * 8 + i;
        if (grow < M) {
            *reinterpret_cast<float4*>(C + (size_t)grow * DD + tx * 8) =
                make_float4(acc[i][0], acc[i][1], acc[i][2], acc[i][3]);
            *reinterpret_cast<float4*>(C + (size_t)grow * DD + tx * 8 + 4) =
                make_float4(acc[i][4], acc[i][5], acc[i][6], acc[i][7]);
        }
    }
}

// ---------------- sparse aggregation: out[n] = sum val * Z[col] + b (opt relu) ----
template <bool RELU>
__global__ __launch_bounds__(256) void agg_kernel(const float* __restrict__ Z,
                                                  const float* __restrict__ b,
                                                  float* __restrict__ out) {
    int warp = (blockIdx.x * blockDim.x + threadIdx.x) >> 5;
    if (warp >= NN) return;
    int lane = threadIdx.x & 31;
    int start = g_rowptr[warp];
    int end   = g_rowptr[warp + 1];
    float4 acc = make_float4(0.f, 0.f, 0.f, 0.f);
    for (int base = start; base < end; base += 32) {
        int idx = base + lane;
        int c = 0; float v = 0.f;
        if (idx < end) { c = g_col[idx]; v = g_val[idx]; }
        int cnt = min(32, end - base);
        for (int j = 0; j < cnt; j++) {
            int   cj = __shfl_sync(0xffffffffu, c, j);
            float vj = __shfl_sync(0xffffffffu, v, j);
            const float4 h4 = *reinterpret_cast<const float4*>(Z + (size_t)cj * DD + lane * 4);
            acc.x = fmaf(vj, h4.x, acc.x);
            acc.y = fmaf(vj, h4.y, acc.y);
            acc.z = fmaf(vj, h4.z, acc.z);
            acc.w = fmaf(vj, h4.w, acc.w);
        }
    }
    const float4 bb = *reinterpret_cast<const float4*>(b + lane * 4);
    acc.x += bb.x; acc.y += bb.y; acc.z += bb.z; acc.w += bb.w;
    if (RELU) {
        acc.x = fmaxf(acc.x, 0.f); acc.y = fmaxf(acc.y, 0.f);
        acc.z = fmaxf(acc.z, 0.f); acc.w = fmaxf(acc.w, 0.f);
    }
    *reinterpret_cast<float4*>(out + (size_t)warp * DD + lane * 4) = acc;
}

// ---------------- layer 5: GEMM [N,128]@[128,2] then 2-wide aggregation -------
__global__ __launch_bounds__(256) void gemm5_kernel(const float* __restrict__ H,
                                                    const float* __restrict__ W5,
                                                    float* __restrict__ Z5) {
    int warp = (blockIdx.x * blockDim.x + threadIdx.x) >> 5;
    if (warp >= NN) return;
    int lane = threadIdx.x & 31;
    const float4 h  = *reinterpret_cast<const float4*>(H + (size_t)warp * DD + lane * 4);
    const float4 w0 = *reinterpret_cast<const float4*>(W5 + lane * 8);
    const float4 w1 = *reinterpret_cast<const float4*>(W5 + lane * 8 + 4);
    // W5 row-major [128][2]: lane covers k = 4*lane .. 4*lane+3
    float p0 = h.x * w0.x + h.y * w0.z + h.z * w1.x + h.w * w1.z;
    float p1 = h.x * w0.y + h.y * w0.w + h.z * w1.y + h.w * w1.w;
#pragma unroll
    for (int off = 16; off > 0; off >>= 1) {
        p0 += __shfl_down_sync(0xffffffffu, p0, off);
        p1 += __shfl_down_sync(0xffffffffu, p1, off);
    }
    if (lane == 0) {
        Z5[(size_t)warp * 2]     = p0;
        Z5[(size_t)warp * 2 + 1] = p1;
    }
}

__global__ __launch_bounds__(256) void agg5_kernel(const float* __restrict__ Z5,
                                                   const float* __restrict__ b5,
                                                   float* __restrict__ out) {
    int n = blockIdx.x * blockDim.x + threadIdx.x;
    if (n >= NN) return;
    float a0 = 0.f, a1 = 0.f;
    int end = g_rowptr[n + 1];
    for (int i = g_rowptr[n]; i < end; i++) {
        int c = g_col[i];
        float v = g_val[i];
        const float2 z = *reinterpret_cast<const float2*>(Z5 + (size_t)c * 2);
        a0 = fmaf(v, z.x, a0);
        a1 = fmaf(v, z.y, a1);
    }
    out[(size_t)n * 2]     = a0 + b5[0];
    out[(size_t)n * 2 + 1] = a1 + b5[1];
}

// ---------------- driver ----------------
extern "C" void kernel_launch(void* const* d_in, const int* in_sizes, int n_in,
                              void* d_out, int out_size) {
    const float* x  = (const float*)d_in[0];
    const int*   ei = (const int*)d_in[1];       // int32! (JAX default, x64 disabled)
    const float* ew = (const float*)d_in[2];
    const float* W1 = (const float*)d_in[3];  const float* b1 = (const float*)d_in[4];
    const float* W2 = (const float*)d_in[5];  const float* b2 = (const float*)d_in[6];
    const float* W3 = (const float*)d_in[7];  const float* b3 = (const float*)d_in[8];
    const float* W4 = (const float*)d_in[9];  const float* b4 = (const float*)d_in[10];
    const float* W5 = (const float*)d_in[11]; const float* b5 = (const float*)d_in[12];
    float* out = (float*)d_out;

    float *Z, *HA, *HB, *Z5;
    cudaGetSymbolAddress((void**)&Z,  g_Z);
    cudaGetSymbolAddress((void**)&HA, g_HA);
    cudaGetSymbolAddress((void**)&HB, g_HB);
    cudaGetSymbolAddress((void**)&Z5, g_Z5);

    const int TB = 256;
    // graph preprocessing
    init_kernel<<<(NN + TB - 1) / TB, TB>>>();
    deg_cnt_kernel<<<(EE + TB - 1) / TB, TB>>>(ei, ew);
    dinv_kernel<<<(NN + TB - 1) / TB, TB>>>();
    scan_kernel<<<1, 1024>>>();
    csr_fill_kernel<<<(EE + NN + TB - 1) / TB, TB>>>(ei, ew);

    const int gemm_blocks = (NN + BM - 1) / BM;
    const int agg_blocks  = (int)(((size_t)NN * 32 + TB - 1) / TB);

    // layer 1
    gemm128_kernel<<<gemm_blocks, 256>>>(x, W1, Z, NN);
    agg_kernel<true><<<agg_blocks, TB>>>(Z, b1, HA);
    // layer 2
    gemm128_kernel<<<gemm_blocks, 256>>>(HA, W2, Z, NN);
    agg_kernel<true><<<agg_blocks, TB>>>(Z, b2, HB);
    // layer 3
    gemm128_kernel<<<gemm_blocks, 256>>>(HB, W3, Z, NN);
    agg_kernel<true><<<agg_blocks, TB>>>(Z, b3, HA);
    // layer 4 (no relu)
    gemm128_kernel<<<gemm_blocks, 256>>>(HA, W4, Z, NN);
    agg_kernel<false><<<agg_blocks, TB>>>(Z, b4, HB);
    // layer 5 (128 -> 2)
    gemm5_kernel<<<agg_blocks, TB>>>(HB, W5, Z5);
    agg5_kernel<<<(NN + TB - 1) / TB, TB>>>(Z5, b5, out);
}

// round 3
// speedup vs baseline: 1.2165x; 1.2165x over previous
#include <cuda_runtime.h>
#include <cuda_bf16.h>
#include <stdint.h>

#define NN 100000
#define EE 1600000
#define DD 128

#define SCAN_CH  1024
#define SCAN_NB  ((NN + SCAN_CH - 1) / SCAN_CH)   // 98

// ---------------- scratch (static __device__, no allocation) ----------------
__device__ float g_deg[NN];            // deg, then dinv in place
__device__ int   g_cnt[NN];
__device__ int   g_rowptr[NN + 1];
__device__ int   g_fill[NN];
__device__ int   g_bsum[SCAN_NB];
__device__ int   g_boff[SCAN_NB];
__device__ int   g_col[EE + NN];
__device__ float g_val[EE + NN];
__device__ float g_Z [NN * DD];
__device__ float g_HA[NN * DD];
__device__ float g_HB[NN * DD];
__device__ float g_Z5[NN * 2];

// ---------------- graph preprocessing ----------------
__global__ void init_kernel() {
    int i = blockIdx.x * blockDim.x + threadIdx.x;
    if (i < NN) {
        g_deg[i]  = 1.0f;   // self-loop weight
        g_cnt[i]  = 1;      // self-loop edge
        g_fill[i] = 0;
    }
}

__global__ void deg_cnt_kernel(const int* __restrict__ ei,
                               const float* __restrict__ w) {
    int e = blockIdx.x * blockDim.x + threadIdx.x;
    if (e >= EE) return;
    int d = ei[EE + e];
    atomicAdd(&g_deg[d], w[e]);
    atomicAdd(&g_cnt[d], 1);
}

__global__ void dinv_kernel() {
    int i = blockIdx.x * blockDim.x + threadIdx.x;
    if (i < NN) g_deg[i] = rsqrtf(g_deg[i]);   // deg >= 1 always (self-loop)
}

// ---- 3-phase exclusive scan of g_cnt -> g_rowptr ----
// phase A: per-block sums (98 blocks x 1024 threads)
__global__ __launch_bounds__(SCAN_CH) void scanA_kernel() {
    __shared__ int s[SCAN_CH];
    int t = threadIdx.x;
    int idx = blockIdx.x * SCAN_CH + t;
    s[t] = (idx < NN) ? g_cnt[idx] : 0;
    __syncthreads();
    for (int off = SCAN_CH >> 1; off > 0; off >>= 1) {
        if (t < off) s[t] += s[t + off];
        __syncthreads();
    }
    if (t == 0) g_bsum[blockIdx.x] = s[0];
}

// phase B: exclusive scan of the 98 block sums (1 tiny block)
__global__ void scanB_kernel() {
    __shared__ int s[SCAN_NB];
    int t = threadIdx.x;
    if (t < SCAN_NB) s[t] = g_bsum[t];
    __syncthreads();
    if (t == 0) {
        int run = 0;
        for (int i = 0; i < SCAN_NB; i++) { int v = s[i]; s[i] = run; run += v; }
    }
    __syncthreads();
    if (t < SCAN_NB) g_boff[t] = s[t];
}

// phase C: per-block Hillis-Steele scan + block offset -> rowptr
__global__ __launch_bounds__(SCAN_CH) void scanC_kernel() {
    __shared__ int s[SCAN_CH];
    int t = threadIdx.x;
    int idx = blockIdx.x * SCAN_CH + t;
    int my = (idx < NN) ? g_cnt[idx] : 0;
    s[t] = my;
    __syncthreads();
    for (int off = 1; off < SCAN_CH; off <<= 1) {
        int u = 0;
        if (t >= off) u = s[t - off];
        __syncthreads();
        s[t] += u;
        __syncthreads();
    }
    if (idx < NN) g_rowptr[idx] = g_boff[blockIdx.x] + s[t] - my;  // exclusive
    if (idx == NN - 1) g_rowptr[NN] = EE + NN;                      // known total
}

__global__ void csr_fill_kernel(const int* __restrict__ ei,
                                const float* __restrict__ w) {
    int e = blockIdx.x * blockDim.x + threadIdx.x;
    if (e < EE) {
        int s = ei[e];
        int d = ei[EE + e];
        int pos = g_rowptr[d] + atomicAdd(&g_fill[d], 1);
        g_col[pos] = s;
        g_val[pos] = g_deg[s] * w[e] * g_deg[d];    // g_deg holds dinv now
    } else if (e < EE + NN) {
        int i = e - EE;
        int pos = g_rowptr[i] + atomicAdd(&g_fill[i], 1);
        float di = g_deg[i];
        g_col[pos] = i;
        g_val[pos] = di * di;
    }
}

// ---------------- dense GEMM: C[M,128] = A[M,128] @ B[128,128] ----------------
#define BM 128
#define BN 128
#define BK 16
__global__ __launch_bounds__(256) void gemm128_kernel(const float* __restrict__ A,
                                                      const float* __restrict__ B,
                                                      float* __restrict__ C, int M) {
    __shared__ float As[BK * BM];   // As[k][m]  (k-major so fragments are LDS.128)
    __shared__ float Bs[BK * BN];   // Bs[k][n]
    const int tid = threadIdx.x;
    const int tx = tid & 15;        // 16 column groups of 8
    const int ty = tid >> 4;        // 16 row groups of 8
    const int m0 = blockIdx.x * BM;

    float acc[8][8];
#pragma unroll
    for (int i = 0; i < 8; i++)
#pragma unroll
        for (int j = 0; j < 8; j++) acc[i][j] = 0.0f;

    for (int k0 = 0; k0 < 128; k0 += BK) {
        // load A tile (transposed into smem)
#pragma unroll
        for (int r2 = 0; r2 < 2; r2++) {
            int li  = tid + r2 * 256;      // 0..511
            int row = li >> 2;             // 0..127
            int cg  = li & 3;              // which float4 of the 16 k's
            float4 a = make_float4(0.f, 0.f, 0.f, 0.f);
            int grow = m0 + row;
            if (grow < M)
                a = *reinterpret_cast<const float4*>(A + (size_t)grow * DD + k0 + cg * 4);
            As[(cg * 4 + 0) * BM + row] = a.x;
            As[(cg * 4 + 1) * BM + row] = a.y;
            As[(cg * 4 + 2) * BM + row] = a.z;
            As[(cg * 4 + 3) * BM + row] = a.w;
        }
        // load B tile (straight copy)
#pragma unroll
        for (int r2 = 0; r2 < 2; r2++) {
            int li  = tid + r2 * 256;
            int row = li >> 5;             // 0..15
            int cg  = li & 31;             // 32 float4 per row
            *reinterpret_cast<float4*>(Bs + row * BN + cg * 4) =
                *reinterpret_cast<const float4*>(B + (size_t)(k0 + row) * 128 + cg * 4);
        }
        __syncthreads();
#pragma unroll
        for (int kk = 0; kk < BK; kk++) {
            float a[8], b[8];
            *reinterpret_cast<float4*>(&a[0]) = *reinterpret_cast<const float4*>(&As[kk * BM + ty * 8]);
            *reinterpret_cast<float4*>(&a[4]) = *reinterpret_cast<const float4*>(&As[kk * BM + ty * 8 + 4]);
            *reinterpret_cast<float4*>(&b[0]) = *reinterpret_cast<const float4*>(&Bs[kk * BN + tx * 8]);
            *reinterpret_cast<float4*>(&b[4]) = *reinterpret_cast<const float4*>(&Bs[kk * BN + tx * 8 + 4]);
#pragma unroll
            for (int i = 0; i < 8; i++)
#pragma unroll
                for (int j = 0; j < 8; j++)
                    acc[i][j] = fmaf(a[i], b[j], acc[i][j]);
        }
        __syncthreads();
    }
#pragma unroll
    for (int i = 0; i < 8; i++) {
        int grow = m0 + ty * 8 + i;
        if (grow < M) {
            *reinterpret_cast<float4*>(C + (size_t)grow * DD + tx * 8) =
                make_float4(acc[i][0], acc[i][1], acc[i][2], acc[i][3]);
            *reinterpret_cast<float4*>(C + (size_t)grow * DD + tx * 8 + 4) =
                make_float4(acc[i][4], acc[i][5], acc[i][6], acc[i][7]);
        }
    }
}

// ---------------- sparse aggregation: out[n] = sum val * Z[col] + b (opt relu) ----
// warp-per-node; lane owns one float4 column slice; (col,val) read uniformly
// (all-lane broadcast load); edges unrolled x4 for MLP.
template <bool RELU>
__global__ __launch_bounds__(256) void agg_kernel(const float* __restrict__ Z,
                                                  const float* __restrict__ b,
                                                  float* __restrict__ out) {
    int warp = (blockIdx.x * blockDim.x + threadIdx.x) >> 5;
    if (warp >= NN) return;
    int lane = threadIdx.x & 31;
    const float* Zl = Z + lane * 4;
    int i   = g_rowptr[warp];
    int end = g_rowptr[warp + 1];
    float4 acc = make_float4(0.f, 0.f, 0.f, 0.f);
    for (; i + 4 <= end; i += 4) {
        int   c0 = g_col[i],   c1 = g_col[i+1],   c2 = g_col[i+2],   c3 = g_col[i+3];
        float v0 = g_val[i],   v1 = g_val[i+1],   v2 = g_val[i+2],   v3 = g_val[i+3];
        const float4 h0 = *reinterpret_cast<const float4*>(Zl + (size_t)c0 * DD);
        const float4 h1 = *reinterpret_cast<const float4*>(Zl + (size_t)c1 * DD);
        const float4 h2 = *reinterpret_cast<const float4*>(Zl + (size_t)c2 * DD);
        const float4 h3 = *reinterpret_cast<const float4*>(Zl + (size_t)c3 * DD);
        acc.x = fmaf(v0, h0.x, acc.x); acc.y = fmaf(v0, h0.y, acc.y);
        acc.z = fmaf(v0, h0.z, acc.z); acc.w = fmaf(v0, h0.w, acc.w);
        acc.x = fmaf(v1, h1.x, acc.x); acc.y = fmaf(v1, h1.y, acc.y);
        acc.z = fmaf(v1, h1.z, acc.z); acc.w = fmaf(v1, h1.w, acc.w);
        acc.x = fmaf(v2, h2.x, acc.x); acc.y = fmaf(v2, h2.y, acc.y);
        acc.z = fmaf(v2, h2.z, acc.z); acc.w = fmaf(v2, h2.w, acc.w);
        acc.x = fmaf(v3, h3.x, acc.x); acc.y = fmaf(v3, h3.y, acc.y);
        acc.z = fmaf(v3, h3.z, acc.z); acc.w = fmaf(v3, h3.w, acc.w);
    }
    for (; i < end; i++) {
        int   c = g_col[i];
        float v = g_val[i];
        const float4 h = *reinterpret_cast<const float4*>(Zl + (size_t)c * DD);
        acc.x = fmaf(v, h.x, acc.x); acc.y = fmaf(v, h.y, acc.y);
        acc.z = fmaf(v, h.z, acc.z); acc.w = fmaf(v, h.w, acc.w);
    }
    const float4 bb = *reinterpret_cast<const float4*>(b + lane * 4);
    acc.x += bb.x; acc.y += bb.y; acc.z += bb.z; acc.w += bb.w;
    if (RELU) {
        acc.x = fmaxf(acc.x, 0.f); acc.y = fmaxf(acc.y, 0.f);
        acc.z = fmaxf(acc.z, 0.f); acc.w = fmaxf(acc.w, 0.f);
    }
    *reinterpret_cast<float4*>(out + (size_t)warp * DD + lane * 4) = acc;
}

// ---------------- layer 5: GEMM [N,128]@[128,2] then 2-wide aggregation -------
__global__ __launch_bounds__(256) void gemm5_kernel(const float* __restrict__ H,
                                                    const float* __restrict__ W5,
                                                    float* __restrict__ Z5) {
    int warp = (blockIdx.x * blockDim.x + threadIdx.x) >> 5;
    if (warp >= NN) return;
    int lane = threadIdx.x & 31;
    const float4 h  = *reinterpret_cast<const float4*>(H + (size_t)warp * DD + lane * 4);
    const float4 w0 = *reinterpret_cast<const float4*>(W5 + lane * 8);
    const float4 w1 = *reinterpret_cast<const float4*>(W5 + lane * 8 + 4);
    // W5 row-major [128][2]: lane covers k = 4*lane .. 4*lane+3
    float p0 = h.x * w0.x + h.y * w0.z + h.z * w1.x + h.w * w1.z;
    float p1 = h.x * w0.y + h.y * w0.w + h.z * w1.y + h.w * w1.w;
#pragma unroll
    for (int off = 16; off > 0; off >>= 1) {
        p0 += __shfl_down_sync(0xffffffffu, p0, off);
        p1 += __shfl_down_sync(0xffffffffu, p1, off);
    }
    if (lane == 0) {
        Z5[(size_t)warp * 2]     = p0;
        Z5[(size_t)warp * 2 + 1] = p1;
    }
}

__global__ __launch_bounds__(256) void agg5_kernel(const float* __restrict__ Z5,
                                                   const float* __restrict__ b5,
                                                   float* __restrict__ out) {
    int n = blockIdx.x * blockDim.x + threadIdx.x;
    if (n >= NN) return;
    float a0 = 0.f, a1 = 0.f;
    int i = g_rowptr[n];
    int end = g_rowptr[n + 1];
    for (; i + 2 <= end; i += 2) {
        int c0 = g_col[i], c1 = g_col[i+1];
        float v0 = g_val[i], v1 = g_val[i+1];
        const float2 z0 = *reinterpret_cast<const float2*>(Z5 + (size_t)c0 * 2);
        const float2 z1 = *reinterpret_cast<const float2*>(Z5 + (size_t)c1 * 2);
        a0 = fmaf(v0, z0.x, a0); a1 = fmaf(v0, z0.y, a1);
        a0 = fmaf(v1, z1.x, a0); a1 = fmaf(v1, z1.y, a1);
    }
    for (; i < end; i++) {
        int c = g_col[i];
        float v = g_val[i];
        const float2 z = *reinterpret_cast<const float2*>(Z5 + (size_t)c * 2);
        a0 = fmaf(v, z.x, a0);
        a1 = fmaf(v, z.y, a1);
    }
    out[(size_t)n * 2]     = a0 + b5[0];
    out[(size_t)n * 2 + 1] = a1 + b5[1];
}

// ---------------- driver ----------------
extern "C" void kernel_launch(void* const* d_in, const int* in_sizes, int n_in,
                              void* d_out, int out_size) {
    const float* x  = (const float*)d_in[0];
    const int*   ei = (const int*)d_in[1];       // int32 (JAX default, x64 disabled)
    const float* ew = (const float*)d_in[2];
    const float* W1 = (const float*)d_in[3];  const float* b1 = (const float*)d_in[4];
    const float* W2 = (const float*)d_in[5];  const float* b2 = (const float*)d_in[6];
    const float* W3 = (const float*)d_in[7];  const float* b3 = (const float*)d_in[8];
    const float* W4 = (const float*)d_in[9];  const float* b4 = (const float*)d_in[10];
    const float* W5 = (const float*)d_in[11]; const float* b5 = (const float*)d_in[12];
    float* out = (float*)d_out;

    float *Z, *HA, *HB, *Z5;
    cudaGetSymbolAddress((void**)&Z,  g_Z);
    cudaGetSymbolAddress((void**)&HA, g_HA);
    cudaGetSymbolAddress((void**)&HB, g_HB);
    cudaGetSymbolAddress((void**)&Z5, g_Z5);

    const int TB = 256;
    // graph preprocessing
    init_kernel<<<(NN + TB - 1) / TB, TB>>>();
    deg_cnt_kernel<<<(EE + TB - 1) / TB, TB>>>(ei, ew);
    dinv_kernel<<<(NN + TB - 1) / TB, TB>>>();
    scanA_kernel<<<SCAN_NB, SCAN_CH>>>();
    scanB_kernel<<<1, 128>>>();
    scanC_kernel<<<SCAN_NB, SCAN_CH>>>();
    csr_fill_kernel<<<(EE + NN + TB - 1) / TB, TB>>>(ei, ew);

    const int gemm_blocks = (NN + BM - 1) / BM;
    const int agg_blocks  = (int)(((size_t)NN * 32 + TB - 1) / TB);

    // layer 1
    gemm128_kernel<<<gemm_blocks, 256>>>(x, W1, Z, NN);
    agg_kernel<true><<<agg_blocks, TB>>>(Z, b1, HA);
    // layer 2
    gemm128_kernel<<<gemm_blocks, 256>>>(HA, W2, Z, NN);
    agg_kernel<true><<<agg_blocks, TB>>>(Z, b2, HB);
    // layer 3
    gemm128_kernel<<<gemm_blocks, 256>>>(HB, W3, Z, NN);
    agg_kernel<true><<<agg_blocks, TB>>>(Z, b3, HA);
    // layer 4 (no relu)
    gemm128_kernel<<<gemm_blocks, 256>>>(HA, W4, Z, NN);
    agg_kernel<false><<<agg_blocks, TB>>>(Z, b4, HB);
    // layer 5 (128 -> 2)
    gemm5_kernel<<<agg_blocks, TB>>>(HB, W5, Z5);
    agg5_kernel<<<(NN + TB - 1) / TB, TB>>>(Z5, b5, out);
}

// round 4
// speedup vs baseline: 1.8281x; 1.5027x over previous
#include <cuda_runtime.h>
#include <cuda_bf16.h>
#include <stdint.h>

#define NN 100000
#define EE 1600000
#define DD 128

#define SCAN_CH  1024
#define SCAN_NB  ((NN + SCAN_CH - 1) / SCAN_CH)   // 98

// ---------------- scratch (static __device__, no allocation) ----------------
__device__ float g_deg[NN];            // deg, then dinv in place
__device__ int   g_cnt[NN];
__device__ int   g_rowptr[NN + 1];
__device__ int   g_fill[NN];
__device__ int   g_bsum[SCAN_NB];
__device__ int   g_boff[SCAN_NB];
__device__ int   g_col[EE + NN];
__device__ float g_val[EE + NN];
__device__ float g_Z [NN * DD];
__device__ float g_HA[NN * DD];
__device__ float g_HB[NN * DD];
__device__ float g_Z5[NN * 2];

// ---------------- graph preprocessing ----------------
__global__ void init_kernel() {
    int i = blockIdx.x * blockDim.x + threadIdx.x;
    if (i < NN) {
        g_deg[i]  = 1.0f;   // self-loop weight
        g_cnt[i]  = 1;      // self-loop edge
        g_fill[i] = 0;
    }
}

__global__ void deg_cnt_kernel(const int* __restrict__ ei,
                               const float* __restrict__ w) {
    int e = blockIdx.x * blockDim.x + threadIdx.x;
    if (e >= EE) return;
    int d = ei[EE + e];
    atomicAdd(&g_deg[d], w[e]);
    atomicAdd(&g_cnt[d], 1);
}

__global__ void dinv_kernel() {
    int i = blockIdx.x * blockDim.x + threadIdx.x;
    if (i < NN) g_deg[i] = rsqrtf(g_deg[i]);   // deg >= 1 always (self-loop)
}

// ---- 3-phase exclusive scan of g_cnt -> g_rowptr ----
__global__ __launch_bounds__(SCAN_CH) void scanA_kernel() {
    __shared__ int s[SCAN_CH];
    int t = threadIdx.x;
    int idx = blockIdx.x * SCAN_CH + t;
    s[t] = (idx < NN) ? g_cnt[idx] : 0;
    __syncthreads();
    for (int off = SCAN_CH >> 1; off > 0; off >>= 1) {
        if (t < off) s[t] += s[t + off];
        __syncthreads();
    }
    if (t == 0) g_bsum[blockIdx.x] = s[0];
}

__global__ void scanB_kernel() {
    __shared__ int s[SCAN_NB];
    int t = threadIdx.x;
    if (t < SCAN_NB) s[t] = g_bsum[t];
    __syncthreads();
    if (t == 0) {
        int run = 0;
        for (int i = 0; i < SCAN_NB; i++) { int v = s[i]; s[i] = run; run += v; }
    }
    __syncthreads();
    if (t < SCAN_NB) g_boff[t] = s[t];
}

__global__ __launch_bounds__(SCAN_CH) void scanC_kernel() {
    __shared__ int s[SCAN_CH];
    int t = threadIdx.x;
    int idx = blockIdx.x * SCAN_CH + t;
    int my = (idx < NN) ? g_cnt[idx] : 0;
    s[t] = my;
    __syncthreads();
    for (int off = 1; off < SCAN_CH; off <<= 1) {
        int u = 0;
        if (t >= off) u = s[t - off];
        __syncthreads();
        s[t] += u;
        __syncthreads();
    }
    if (idx < NN) g_rowptr[idx] = g_boff[blockIdx.x] + s[t] - my;  // exclusive
    if (idx == NN - 1) g_rowptr[NN] = EE + NN;                      // known total
}

__global__ void csr_fill_kernel(const int* __restrict__ ei,
                                const float* __restrict__ w) {
    int e = blockIdx.x * blockDim.x + threadIdx.x;
    if (e < EE) {
        int s = ei[e];
        int d = ei[EE + e];
        int pos = g_rowptr[d] + atomicAdd(&g_fill[d], 1);
        g_col[pos] = s;
        g_val[pos] = g_deg[s] * w[e] * g_deg[d];    // g_deg holds dinv now
    } else if (e < EE + NN) {
        int i = e - EE;
        int pos = g_rowptr[i] + atomicAdd(&g_fill[i], 1);
        float di = g_deg[i];
        g_col[pos] = i;
        g_val[pos] = di * di;
    }
}

// ---------------- tf32 tensor-core GEMM: C[M,128] = A[M,128] @ B[128,128] -----
// CTA tile 128x128x32, 8 warps in 4(M) x 2(N); warp tile 32x64 = 2x8 m16n8k8.
// Smem strides chosen for conflict-free fragment LDS: As 36, Bs 136.
#define GBM 128
#define GBK 32
#define AS_STRIDE 36
#define BS_STRIDE 136

__device__ __forceinline__ uint32_t f2tf32(float f) {
    uint32_t u;
    asm("cvt.rna.tf32.f32 %0, %1;" : "=r"(u) : "f"(f));
    return u;
}

__global__ __launch_bounds__(256) void gemm_tf32_kernel(const float* __restrict__ A,
                                                        const float* __restrict__ B,
                                                        float* __restrict__ C, int M) {
    __shared__ uint32_t As[GBM * AS_STRIDE];   // [m][k]
    __shared__ uint32_t Bs[GBK * BS_STRIDE];   // [k][n]
    const int tid  = threadIdx.x;
    const int wid  = tid >> 5;
    const int lane = tid & 31;
    const int g    = lane >> 2;     // 0..7
    const int tig  = lane & 3;      // 0..3
    const int warp_m = wid & 3;     // 0..3  (32 rows each)
    const int warp_n = wid >> 2;    // 0..1  (64 cols each)
    const int m0 = blockIdx.x * GBM;

    float acc[2][8][4];
#pragma unroll
    for (int mi = 0; mi < 2; mi++)
#pragma unroll
        for (int ni = 0; ni < 8; ni++)
#pragma unroll
            for (int q = 0; q < 4; q++) acc[mi][ni][q] = 0.0f;

    for (int k0 = 0; k0 < 128; k0 += GBK) {
        // A tile 128x32 -> As (tf32-converted)
#pragma unroll
        for (int it = 0; it < 4; it++) {
            int idx = tid + it * 256;           // 0..1023
            int row = idx >> 3;                 // 0..127
            int c4  = (idx & 7) * 4;            // 0..28
            float4 a = make_float4(0.f, 0.f, 0.f, 0.f);
            if (m0 + row < M)
                a = *reinterpret_cast<const float4*>(A + (size_t)(m0 + row) * DD + k0 + c4);
            uint4 u = make_uint4(f2tf32(a.x), f2tf32(a.y), f2tf32(a.z), f2tf32(a.w));
            *reinterpret_cast<uint4*>(&As[row * AS_STRIDE + c4]) = u;
        }
        // B tile 32x128 -> Bs (tf32-converted)
#pragma unroll
        for (int it = 0; it < 4; it++) {
            int idx = tid + it * 256;
            int row = idx >> 5;                 // 0..31
            int c4  = (idx & 31) * 4;           // 0..124
            float4 b = *reinterpret_cast<const float4*>(B + (size_t)(k0 + row) * 128 + c4);
            uint4 u = make_uint4(f2tf32(b.x), f2tf32(b.y), f2tf32(b.z), f2tf32(b.w));
            *reinterpret_cast<uint4*>(&Bs[row * BS_STRIDE + c4]) = u;
        }
        __syncthreads();
#pragma unroll
        for (int ks = 0; ks < 4; ks++) {
            const int kk = ks * 8;
            uint32_t af[2][4], bf[8][2];
#pragma unroll
            for (int mi = 0; mi < 2; mi++) {
                int rm = warp_m * 32 + mi * 16;
                af[mi][0] = As[(rm + g    ) * AS_STRIDE + kk + tig    ];
                af[mi][1] = As[(rm + g + 8) * AS_STRIDE + kk + tig    ];
                af[mi][2] = As[(rm + g    ) * AS_STRIDE + kk + tig + 4];
                af[mi][3] = As[(rm + g + 8) * AS_STRIDE + kk + tig + 4];
            }
#pragma unroll
            for (int ni = 0; ni < 8; ni++) {
                int nb = warp_n * 64 + ni * 8;
                bf[ni][0] = Bs[(kk + tig    ) * BS_STRIDE + nb + g];
                bf[ni][1] = Bs[(kk + tig + 4) * BS_STRIDE + nb + g];
            }
#pragma unroll
            for (int mi = 0; mi < 2; mi++)
#pragma unroll
                for (int ni = 0; ni < 8; ni++) {
                    asm volatile(
                        "mma.sync.aligned.m16n8k8.row.col.f32.tf32.tf32.f32 "
                        "{%0,%1,%2,%3}, {%4,%5,%6,%7}, {%8,%9}, {%0,%1,%2,%3};\n"
                        : "+f"(acc[mi][ni][0]), "+f"(acc[mi][ni][1]),
                          "+f"(acc[mi][ni][2]), "+f"(acc[mi][ni][3])
                        : "r"(af[mi][0]), "r"(af[mi][1]), "r"(af[mi][2]), "r"(af[mi][3]),
                          "r"(bf[ni][0]), "r"(bf[ni][1]));
                }
        }
        __syncthreads();
    }
    // epilogue: c0,c1 -> (row g, col tig*2, tig*2+1); c2,c3 -> row g+8
#pragma unroll
    for (int mi = 0; mi < 2; mi++) {
        int row0 = m0 + warp_m * 32 + mi * 16 + g;
#pragma unroll
        for (int ni = 0; ni < 8; ni++) {
            int col = warp_n * 64 + ni * 8 + tig * 2;
            if (row0 < M)
                *reinterpret_cast<float2*>(C + (size_t)row0 * DD + col) =
                    make_float2(acc[mi][ni][0], acc[mi][ni][1]);
            if (row0 + 8 < M)
                *reinterpret_cast<float2*>(C + (size_t)(row0 + 8) * DD + col) =
                    make_float2(acc[mi][ni][2], acc[mi][ni][3]);
        }
    }
}

// ---------------- sparse aggregation: out[n] = sum val * Z[col] + b (opt relu) ----
template <bool RELU>
__global__ __launch_bounds__(256) void agg_kernel(const float* __restrict__ Z,
                                                  const float* __restrict__ b,
                                                  float* __restrict__ out) {
    int warp = (blockIdx.x * blockDim.x + threadIdx.x) >> 5;
    if (warp >= NN) return;
    int lane = threadIdx.x & 31;
    const float* Zl = Z + lane * 4;
    int i   = g_rowptr[warp];
    int end = g_rowptr[warp + 1];
    float4 acc = make_float4(0.f, 0.f, 0.f, 0.f);
    for (; i + 4 <= end; i += 4) {
        int   c0 = g_col[i],   c1 = g_col[i+1],   c2 = g_col[i+2],   c3 = g_col[i+3];
        float v0 = g_val[i],   v1 = g_val[i+1],   v2 = g_val[i+2],   v3 = g_val[i+3];
        const float4 h0 = *reinterpret_cast<const float4*>(Zl + (size_t)c0 * DD);
        const float4 h1 = *reinterpret_cast<const float4*>(Zl + (size_t)c1 * DD);
        const float4 h2 = *reinterpret_cast<const float4*>(Zl + (size_t)c2 * DD);
        const float4 h3 = *reinterpret_cast<const float4*>(Zl + (size_t)c3 * DD);
        acc.x = fmaf(v0, h0.x, acc.x); acc.y = fmaf(v0, h0.y, acc.y);
        acc.z = fmaf(v0, h0.z, acc.z); acc.w = fmaf(v0, h0.w, acc.w);
        acc.x = fmaf(v1, h1.x, acc.x); acc.y = fmaf(v1, h1.y, acc.y);
        acc.z = fmaf(v1, h1.z, acc.z); acc.w = fmaf(v1, h1.w, acc.w);
        acc.x = fmaf(v2, h2.x, acc.x); acc.y = fmaf(v2, h2.y, acc.y);
        acc.z = fmaf(v2, h2.z, acc.z); acc.w = fmaf(v2, h2.w, acc.w);
        acc.x = fmaf(v3, h3.x, acc.x); acc.y = fmaf(v3, h3.y, acc.y);
        acc.z = fmaf(v3, h3.z, acc.z); acc.w = fmaf(v3, h3.w, acc.w);
    }
    for (; i < end; i++) {
        int   c = g_col[i];
        float v = g_val[i];
        const float4 h = *reinterpret_cast<const float4*>(Zl + (size_t)c * DD);
        acc.x = fmaf(v, h.x, acc.x); acc.y = fmaf(v, h.y, acc.y);
        acc.z = fmaf(v, h.z, acc.z); acc.w = fmaf(v, h.w, acc.w);
    }
    const float4 bb = *reinterpret_cast<const float4*>(b + lane * 4);
    acc.x += bb.x; acc.y += bb.y; acc.z += bb.z; acc.w += bb.w;
    if (RELU) {
        acc.x = fmaxf(acc.x, 0.f); acc.y = fmaxf(acc.y, 0.f);
        acc.z = fmaxf(acc.z, 0.f); acc.w = fmaxf(acc.w, 0.f);
    }
    *reinterpret_cast<float4*>(out + (size_t)warp * DD + lane * 4) = acc;
}

// ---------------- layer 5: GEMM [N,128]@[128,2] then 2-wide aggregation -------
__global__ __launch_bounds__(256) void gemm5_kernel(const float* __restrict__ H,
                                                    const float* __restrict__ W5,
                                                    float* __restrict__ Z5) {
    int warp = (blockIdx.x * blockDim.x + threadIdx.x) >> 5;
    if (warp >= NN) return;
    int lane = threadIdx.x & 31;
    const float4 h  = *reinterpret_cast<const float4*>(H + (size_t)warp * DD + lane * 4);
    const float4 w0 = *reinterpret_cast<const float4*>(W5 + lane * 8);
    const float4 w1 = *reinterpret_cast<const float4*>(W5 + lane * 8 + 4);
    float p0 = h.x * w0.x + h.y * w0.z + h.z * w1.x + h.w * w1.z;
    float p1 = h.x * w0.y + h.y * w0.w + h.z * w1.y + h.w * w1.w;
#pragma unroll
    for (int off = 16; off > 0; off >>= 1) {
        p0 += __shfl_down_sync(0xffffffffu, p0, off);
        p1 += __shfl_down_sync(0xffffffffu, p1, off);
    }
    if (lane == 0) {
        Z5[(size_t)warp * 2]     = p0;
        Z5[(size_t)warp * 2 + 1] = p1;
    }
}

__global__ __launch_bounds__(256) void agg5_kernel(const float* __restrict__ Z5,
                                                   const float* __restrict__ b5,
                                                   float* __restrict__ out) {
    int n = blockIdx.x * blockDim.x + threadIdx.x;
    if (n >= NN) return;
    float a0 = 0.f, a1 = 0.f;
    int i = g_rowptr[n];
    int end = g_rowptr[n + 1];
    for (; i + 2 <= end; i += 2) {
        int c0 = g_col[i], c1 = g_col[i+1];
        float v0 = g_val[i], v1 = g_val[i+1];
        const float2 z0 = *reinterpret_cast<const float2*>(Z5 + (size_t)c0 * 2);
        const float2 z1 = *reinterpret_cast<const float2*>(Z5 + (size_t)c1 * 2);
        a0 = fmaf(v0, z0.x, a0); a1 = fmaf(v0, z0.y, a1);
        a0 = fmaf(v1, z1.x, a0); a1 = fmaf(v1, z1.y, a1);
    }
    for (; i < end; i++) {
        int c = g_col[i];
        float v = g_val[i];
        const float2 z = *reinterpret_cast<const float2*>(Z5 + (size_t)c * 2);
        a0 = fmaf(v, z.x, a0);
        a1 = fmaf(v, z.y, a1);
    }
    out[(size_t)n * 2]     = a0 + b5[0];
    out[(size_t)n * 2 + 1] = a1 + b5[1];
}

// ---------------- driver ----------------
extern "C" void kernel_launch(void* const* d_in, const int* in_sizes, int n_in,
                              void* d_out, int out_size) {
    const float* x  = (const float*)d_in[0];
    const int*   ei = (const int*)d_in[1];       // int32 (JAX default, x64 disabled)
    const float* ew = (const float*)d_in[2];
    const float* W1 = (const float*)d_in[3];  const float* b1 = (const float*)d_in[4];
    const float* W2 = (const float*)d_in[5];  const float* b2 = (const float*)d_in[6];
    const float* W3 = (const float*)d_in[7];  const float* b3 = (const float*)d_in[8];
    const float* W4 = (const float*)d_in[9];  const float* b4 = (const float*)d_in[10];
    const float* W5 = (const float*)d_in[11]; const float* b5 = (const float*)d_in[12];
    float* out = (float*)d_out;

    float *Z, *HA, *HB, *Z5;
    cudaGetSymbolAddress((void**)&Z,  g_Z);
    cudaGetSymbolAddress((void**)&HA, g_HA);
    cudaGetSymbolAddress((void**)&HB, g_HB);
    cudaGetSymbolAddress((void**)&Z5, g_Z5);

    const int TB = 256;
    // graph preprocessing
    init_kernel<<<(NN + TB - 1) / TB, TB>>>();
    deg_cnt_kernel<<<(EE + TB - 1) / TB, TB>>>(ei, ew);
    dinv_kernel<<<(NN + TB - 1) / TB, TB>>>();
    scanA_kernel<<<SCAN_NB, SCAN_CH>>>();
    scanB_kernel<<<1, 128>>>();
    scanC_kernel<<<SCAN_NB, SCAN_CH>>>();
    csr_fill_kernel<<<(EE + NN + TB - 1) / TB, TB>>>(ei, ew);

    const int gemm_blocks = (NN + GBM - 1) / GBM;
    const int agg_blocks  = (int)(((size_t)NN * 32 + TB - 1) / TB);

    // layer 1
    gemm_tf32_kernel<<<gemm_blocks, 256>>>(x, W1, Z, NN);
    agg_kernel<true><<<agg_blocks, TB>>>(Z, b1, HA);
    // layer 2
    gemm_tf32_kernel<<<gemm_blocks, 256>>>(HA, W2, Z, NN);
    agg_kernel<true><<<agg_blocks, TB>>>(Z, b2, HB);
    // layer 3
    gemm_tf32_kernel<<<gemm_blocks, 256>>>(HB, W3, Z, NN);
    agg_kernel<true><<<agg_blocks, TB>>>(Z, b3, HA);
    // layer 4 (no relu)
    gemm_tf32_kernel<<<gemm_blocks, 256>>>(HA, W4, Z, NN);
    agg_kernel<false><<<agg_blocks, TB>>>(Z, b4, HB);
    // layer 5 (128 -> 2)
    gemm5_kernel<<<agg_blocks, TB>>>(HB, W5, Z5);
    agg5_kernel<<<(NN + TB - 1) / TB, TB>>>(Z5, b5, out);
}

// round 5
// speedup vs baseline: 1.9769x; 1.0814x over previous
#include <cuda_runtime.h>
#include <cuda_fp16.h>
#include <stdint.h>

#define NN 100000
#define EE 1600000
#define DD 128

#define SCAN_CH  1024
#define SCAN_NB  ((NN + SCAN_CH - 1) / SCAN_CH)   // 98

// ---------------- scratch (static __device__, no allocation) ----------------
__device__ float  g_deg[NN];            // deg, then dinv in place
__device__ int    g_cnt[NN];
__device__ int    g_rowptr[NN + 1];
__device__ int    g_fill[NN];
__device__ int    g_bsum[SCAN_NB];
__device__ int    g_boff[SCAN_NB];
__device__ int    g_col[EE + NN];
__device__ float  g_val[EE + NN];
__device__ __half g_Zh[NN * DD];        // post-GEMM features, fp16 (gather source)
__device__ float  g_HA[NN * DD];
__device__ float  g_HB[NN * DD];
__device__ float  g_Z5[NN * 2];

// ---------------- graph preprocessing ----------------
__global__ void init_kernel() {
    int i = blockIdx.x * blockDim.x + threadIdx.x;
    if (i < NN) {
        g_deg[i]  = 1.0f;   // self-loop weight
        g_cnt[i]  = 1;      // self-loop edge
        g_fill[i] = 0;
    }
}

__global__ void deg_cnt_kernel(const int* __restrict__ ei,
                               const float* __restrict__ w) {
    int e = blockIdx.x * blockDim.x + threadIdx.x;
    if (e >= EE) return;
    int d = ei[EE + e];
    atomicAdd(&g_deg[d], w[e]);
    atomicAdd(&g_cnt[d], 1);
}

__global__ void dinv_kernel() {
    int i = blockIdx.x * blockDim.x + threadIdx.x;
    if (i < NN) g_deg[i] = rsqrtf(g_deg[i]);   // deg >= 1 always (self-loop)
}

// ---- 3-phase exclusive scan of g_cnt -> g_rowptr ----
__global__ __launch_bounds__(SCAN_CH) void scanA_kernel() {
    __shared__ int s[SCAN_CH];
    int t = threadIdx.x;
    int idx = blockIdx.x * SCAN_CH + t;
    s[t] = (idx < NN) ? g_cnt[idx] : 0;
    __syncthreads();
    for (int off = SCAN_CH >> 1; off > 0; off >>= 1) {
        if (t < off) s[t] += s[t + off];
        __syncthreads();
    }
    if (t == 0) g_bsum[blockIdx.x] = s[0];
}

__global__ void scanB_kernel() {
    __shared__ int s[SCAN_NB];
    int t = threadIdx.x;
    if (t < SCAN_NB) s[t] = g_bsum[t];
    __syncthreads();
    if (t == 0) {
        int run = 0;
        for (int i = 0; i < SCAN_NB; i++) { int v = s[i]; s[i] = run; run += v; }
    }
    __syncthreads();
    if (t < SCAN_NB) g_boff[t] = s[t];
}

__global__ __launch_bounds__(SCAN_CH) void scanC_kernel() {
    __shared__ int s[SCAN_CH];
    int t = threadIdx.x;
    int idx = blockIdx.x * SCAN_CH + t;
    int my = (idx < NN) ? g_cnt[idx] : 0;
    s[t] = my;
    __syncthreads();
    for (int off = 1; off < SCAN_CH; off <<= 1) {
        int u = 0;
        if (t >= off) u = s[t - off];
        __syncthreads();
        s[t] += u;
        __syncthreads();
    }
    if (idx < NN) g_rowptr[idx] = g_boff[blockIdx.x] + s[t] - my;  // exclusive
    if (idx == NN - 1) g_rowptr[NN] = EE + NN;                      // known total
}

__global__ void csr_fill_kernel(const int* __restrict__ ei,
                                const float* __restrict__ w) {
    int e = blockIdx.x * blockDim.x + threadIdx.x;
    if (e < EE) {
        int s = ei[e];
        int d = ei[EE + e];
        int pos = g_rowptr[d] + atomicAdd(&g_fill[d], 1);
        g_col[pos] = s;
        g_val[pos] = g_deg[s] * w[e] * g_deg[d];    // g_deg holds dinv now
    } else if (e < EE + NN) {
        int i = e - EE;
        int pos = g_rowptr[i] + atomicAdd(&g_fill[i], 1);
        float di = g_deg[i];
        g_col[pos] = i;
        g_val[pos] = di * di;
    }
}

// ---------------- tf32 tensor-core GEMM: Zh[M,128] = A[M,128] @ B[128,128] ----
// CTA tile 128x128x32, 8 warps in 4(M) x 2(N); warp tile 32x64 = 2x8 m16n8k8.
// Epilogue converts fp32 accumulators to fp16 (gather-friendly storage).
#define GBM 128
#define GBK 32
#define AS_STRIDE 36
#define BS_STRIDE 136

__device__ __forceinline__ uint32_t f2tf32(float f) {
    uint32_t u;
    asm("cvt.rna.tf32.f32 %0, %1;" : "=r"(u) : "f"(f));
    return u;
}

__global__ __launch_bounds__(256) void gemm_tf32_kernel(const float* __restrict__ A,
                                                        const float* __restrict__ B,
                                                        __half* __restrict__ C, int M) {
    __shared__ uint32_t As[GBM * AS_STRIDE];   // [m][k]
    __shared__ uint32_t Bs[GBK * BS_STRIDE];   // [k][n]
    const int tid  = threadIdx.x;
    const int wid  = tid >> 5;
    const int lane = tid & 31;
    const int g    = lane >> 2;     // 0..7
    const int tig  = lane & 3;      // 0..3
    const int warp_m = wid & 3;     // 0..3  (32 rows each)
    const int warp_n = wid >> 2;    // 0..1  (64 cols each)
    const int m0 = blockIdx.x * GBM;

    float acc[2][8][4];
#pragma unroll
    for (int mi = 0; mi < 2; mi++)
#pragma unroll
        for (int ni = 0; ni < 8; ni++)
#pragma unroll
            for (int q = 0; q < 4; q++) acc[mi][ni][q] = 0.0f;

    for (int k0 = 0; k0 < 128; k0 += GBK) {
        // A tile 128x32 -> As (tf32-converted)
#pragma unroll
        for (int it = 0; it < 4; it++) {
            int idx = tid + it * 256;           // 0..1023
            int row = idx >> 3;                 // 0..127
            int c4  = (idx & 7) * 4;            // 0..28
            float4 a = make_float4(0.f, 0.f, 0.f, 0.f);
            if (m0 + row < M)
                a = *reinterpret_cast<const float4*>(A + (size_t)(m0 + row) * DD + k0 + c4);
            uint4 u = make_uint4(f2tf32(a.x), f2tf32(a.y), f2tf32(a.z), f2tf32(a.w));
            *reinterpret_cast<uint4*>(&As[row * AS_STRIDE + c4]) = u;
        }
        // B tile 32x128 -> Bs (tf32-converted)
#pragma unroll
        for (int it = 0; it < 4; it++) {
            int idx = tid + it * 256;
            int row = idx >> 5;                 // 0..31
            int c4  = (idx & 31) * 4;           // 0..124
            float4 b = *reinterpret_cast<const float4*>(B + (size_t)(k0 + row) * 128 + c4);
            uint4 u = make_uint4(f2tf32(b.x), f2tf32(b.y), f2tf32(b.z), f2tf32(b.w));
            *reinterpret_cast<uint4*>(&Bs[row * BS_STRIDE + c4]) = u;
        }
        __syncthreads();
#pragma unroll
        for (int ks = 0; ks < 4; ks++) {
            const int kk = ks * 8;
            uint32_t af[2][4], bf[8][2];
#pragma unroll
            for (int mi = 0; mi < 2; mi++) {
                int rm = warp_m * 32 + mi * 16;
                af[mi][0] = As[(rm + g    ) * AS_STRIDE + kk + tig    ];
                af[mi][1] = As[(rm + g + 8) * AS_STRIDE + kk + tig    ];
                af[mi][2] = As[(rm + g    ) * AS_STRIDE + kk + tig + 4];
                af[mi][3] = As[(rm + g + 8) * AS_STRIDE + kk + tig + 4];
            }
#pragma unroll
            for (int ni = 0; ni < 8; ni++) {
                int nb = warp_n * 64 + ni * 8;
                bf[ni][0] = Bs[(kk + tig    ) * BS_STRIDE + nb + g];
                bf[ni][1] = Bs[(kk + tig + 4) * BS_STRIDE + nb + g];
            }
#pragma unroll
            for (int mi = 0; mi < 2; mi++)
#pragma unroll
                for (int ni = 0; ni < 8; ni++) {
                    asm volatile(
                        "mma.sync.aligned.m16n8k8.row.col.f32.tf32.tf32.f32 "
                        "{%0,%1,%2,%3}, {%4,%5,%6,%7}, {%8,%9}, {%0,%1,%2,%3};\n"
                        : "+f"(acc[mi][ni][0]), "+f"(acc[mi][ni][1]),
                          "+f"(acc[mi][ni][2]), "+f"(acc[mi][ni][3])
                        : "r"(af[mi][0]), "r"(af[mi][1]), "r"(af[mi][2]), "r"(af[mi][3]),
                          "r"(bf[ni][0]), "r"(bf[ni][1]));
                }
        }
        __syncthreads();
    }
    // epilogue: fp32 acc -> fp16 pairs. c0,c1 -> row g; c2,c3 -> row g+8
#pragma unroll
    for (int mi = 0; mi < 2; mi++) {
        int row0 = m0 + warp_m * 32 + mi * 16 + g;
#pragma unroll
        for (int ni = 0; ni < 8; ni++) {
            int col = warp_n * 64 + ni * 8 + tig * 2;
            if (row0 < M)
                *reinterpret_cast<__half2*>(C + (size_t)row0 * DD + col) =
                    __floats2half2_rn(acc[mi][ni][0], acc[mi][ni][1]);
            if (row0 + 8 < M)
                *reinterpret_cast<__half2*>(C + (size_t)(row0 + 8) * DD + col) =
                    __floats2half2_rn(acc[mi][ni][2], acc[mi][ni][3]);
        }
    }
}

// ---------------- sparse aggregation: out[n] = sum val * Zh[col] + b (opt relu) --
// warp-per-node; lane owns 4 channels (uint2 = 4 halves); fp32 accumulate.
template <bool RELU>
__global__ __launch_bounds__(256) void agg_kernel(const __half* __restrict__ Z,
                                                  const float* __restrict__ b,
                                                  float* __restrict__ out) {
    int warp = (blockIdx.x * blockDim.x + threadIdx.x) >> 5;
    if (warp >= NN) return;
    int lane = threadIdx.x & 31;
    const __half* Zl = Z + lane * 4;
    int i   = g_rowptr[warp];
    int end = g_rowptr[warp + 1];
    float4 acc = make_float4(0.f, 0.f, 0.f, 0.f);
    for (; i + 4 <= end; i += 4) {
        int   c0 = g_col[i],   c1 = g_col[i+1],   c2 = g_col[i+2],   c3 = g_col[i+3];
        float v0 = g_val[i],   v1 = g_val[i+1],   v2 = g_val[i+2],   v3 = g_val[i+3];
        const __half2* p0 = reinterpret_cast<const __half2*>(Zl + (size_t)c0 * DD);
        const __half2* p1 = reinterpret_cast<const __half2*>(Zl + (size_t)c1 * DD);
        const __half2* p2 = reinterpret_cast<const __half2*>(Zl + (size_t)c2 * DD);
        const __half2* p3 = reinterpret_cast<const __half2*>(Zl + (size_t)c3 * DD);
        __half2 a0 = p0[0], b0 = p0[1];
        __half2 a1 = p1[0], b1 = p1[1];
        __half2 a2 = p2[0], b2 = p2[1];
        __half2 a3 = p3[0], b3 = p3[1];
        float2 f;
        f = __half22float2(a0); acc.x = fmaf(v0, f.x, acc.x); acc.y = fmaf(v0, f.y, acc.y);
        f = __half22float2(b0); acc.z = fmaf(v0, f.x, acc.z); acc.w = fmaf(v0, f.y, acc.w);
        f = __half22float2(a1); acc.x = fmaf(v1, f.x, acc.x); acc.y = fmaf(v1, f.y, acc.y);
        f = __half22float2(b1); acc.z = fmaf(v1, f.x, acc.z); acc.w = fmaf(v1, f.y, acc.w);
        f = __half22float2(a2); acc.x = fmaf(v2, f.x, acc.x); acc.y = fmaf(v2, f.y, acc.y);
        f = __half22float2(b2); acc.z = fmaf(v2, f.x, acc.z); acc.w = fmaf(v2, f.y, acc.w);
        f = __half22float2(a3); acc.x = fmaf(v3, f.x, acc.x); acc.y = fmaf(v3, f.y, acc.y);
        f = __half22float2(b3); acc.z = fmaf(v3, f.x, acc.z); acc.w = fmaf(v3, f.y, acc.w);
    }
    for (; i < end; i++) {
        int   c = g_col[i];
        float v = g_val[i];
        const __half2* p = reinterpret_cast<const __half2*>(Zl + (size_t)c * DD);
        __half2 a = p[0], d = p[1];
        float2 f;
        f = __half22float2(a); acc.x = fmaf(v, f.x, acc.x); acc.y = fmaf(v, f.y, acc.y);
        f = __half22float2(d); acc.z = fmaf(v, f.x, acc.z); acc.w = fmaf(v, f.y, acc.w);
    }
    const float4 bb = *reinterpret_cast<const float4*>(b + lane * 4);
    acc.x += bb.x; acc.y += bb.y; acc.z += bb.z; acc.w += bb.w;
    if (RELU) {
        acc.x = fmaxf(acc.x, 0.f); acc.y = fmaxf(acc.y, 0.f);
        acc.z = fmaxf(acc.z, 0.f); acc.w = fmaxf(acc.w, 0.f);
    }
    *reinterpret_cast<float4*>(out + (size_t)warp * DD + lane * 4) = acc;
}

// ---------------- layer 5: GEMM [N,128]@[128,2] then 2-wide aggregation -------
__global__ __launch_bounds__(256) void gemm5_kernel(const float* __restrict__ H,
                                                    const float* __restrict__ W5,
                                                    float* __restrict__ Z5) {
    int warp = (blockIdx.x * blockDim.x + threadIdx.x) >> 5;
    if (warp >= NN) return;
    int lane = threadIdx.x & 31;
    const float4 h  = *reinterpret_cast<const float4*>(H + (size_t)warp * DD + lane * 4);
    const float4 w0 = *reinterpret_cast<const float4*>(W5 + lane * 8);
    const float4 w1 = *reinterpret_cast<const float4*>(W5 + lane * 8 + 4);
    float p0 = h.x * w0.x + h.y * w0.z + h.z * w1.x + h.w * w1.z;
    float p1 = h.x * w0.y + h.y * w0.w + h.z * w1.y + h.w * w1.w;
#pragma unroll
    for (int off = 16; off > 0; off >>= 1) {
        p0 += __shfl_down_sync(0xffffffffu, p0, off);
        p1 += __shfl_down_sync(0xffffffffu, p1, off);
    }
    if (lane == 0) {
        Z5[(size_t)warp * 2]     = p0;
        Z5[(size_t)warp * 2 + 1] = p1;
    }
}

__global__ __launch_bounds__(256) void agg5_kernel(const float* __restrict__ Z5,
                                                   const float* __restrict__ b5,
                                                   float* __restrict__ out) {
    int n = blockIdx.x * blockDim.x + threadIdx.x;
    if (n >= NN) return;
    float a0 = 0.f, a1 = 0.f;
    int i = g_rowptr[n];
    int end = g_rowptr[n + 1];
    for (; i + 2 <= end; i += 2) {
        int c0 = g_col[i], c1 = g_col[i+1];
        float v0 = g_val[i], v1 = g_val[i+1];
        const float2 z0 = *reinterpret_cast<const float2*>(Z5 + (size_t)c0 * 2);
        const float2 z1 = *reinterpret_cast<const float2*>(Z5 + (size_t)c1 * 2);
        a0 = fmaf(v0, z0.x, a0); a1 = fmaf(v0, z0.y, a1);
        a0 = fmaf(v1, z1.x, a0); a1 = fmaf(v1, z1.y, a1);
    }
    for (; i < end; i++) {
        int c = g_col[i];
        float v = g_val[i];
        const float2 z = *reinterpret_cast<const float2*>(Z5 + (size_t)c * 2);
        a0 = fmaf(v, z.x, a0);
        a1 = fmaf(v, z.y, a1);
    }
    out[(size_t)n * 2]     = a0 + b5[0];
    out[(size_t)n * 2 + 1] = a1 + b5[1];
}

// ---------------- driver ----------------
extern "C" void kernel_launch(void* const* d_in, const int* in_sizes, int n_in,
                              void* d_out, int out_size) {
    const float* x  = (const float*)d_in[0];
    const int*   ei = (const int*)d_in[1];       // int32 (JAX default, x64 disabled)
    const float* ew = (const float*)d_in[2];
    const float* W1 = (const float*)d_in[3];  const float* b1 = (const float*)d_in[4];
    const float* W2 = (const float*)d_in[5];  const float* b2 = (const float*)d_in[6];
    const float* W3 = (const float*)d_in[7];  const float* b3 = (const float*)d_in[8];
    const float* W4 = (const float*)d_in[9];  const float* b4 = (const float*)d_in[10];
    const float* W5 = (const float*)d_in[11]; const float* b5 = (const float*)d_in[12];
    float* out = (float*)d_out;

    __half *Zh; float *HA, *HB, *Z5;
    cudaGetSymbolAddress((void**)&Zh, g_Zh);
    cudaGetSymbolAddress((void**)&HA, g_HA);
    cudaGetSymbolAddress((void**)&HB, g_HB);
    cudaGetSymbolAddress((void**)&Z5, g_Z5);

    const int TB = 256;
    // graph preprocessing
    init_kernel<<<(NN + TB - 1) / TB, TB>>>();
    deg_cnt_kernel<<<(EE + TB - 1) / TB, TB>>>(ei, ew);
    dinv_kernel<<<(NN + TB - 1) / TB, TB>>>();
    scanA_kernel<<<SCAN_NB, SCAN_CH>>>();
    scanB_kernel<<<1, 128>>>();
    scanC_kernel<<<SCAN_NB, SCAN_CH>>>();
    csr_fill_kernel<<<(EE + NN + TB - 1) / TB, TB>>>(ei, ew);

    const int gemm_blocks = (NN + GBM - 1) / GBM;
    const int agg_blocks  = (int)(((size_t)NN * 32 + TB - 1) / TB);

    // layer 1
    gemm_tf32_kernel<<<gemm_blocks, 256>>>(x, W1, Zh, NN);
    agg_kernel<true><<<agg_blocks, TB>>>(Zh, b1, HA);
    // layer 2
    gemm_tf32_kernel<<<gemm_blocks, 256>>>(HA, W2, Zh, NN);
    agg_kernel<true><<<agg_blocks, TB>>>(Zh, b2, HB);
    // layer 3
    gemm_tf32_kernel<<<gemm_blocks, 256>>>(HB, W3, Zh, NN);
    agg_kernel<true><<<agg_blocks, TB>>>(Zh, b3, HA);
    // layer 4 (no relu)
    gemm_tf32_kernel<<<gemm_blocks, 256>>>(HA, W4, Zh, NN);
    agg_kernel<false><<<agg_blocks, TB>>>(Zh, b4, HB);
    // layer 5 (128 -> 2)
    gemm5_kernel<<<agg_blocks, TB>>>(HB, W5, Z5);
    agg5_kernel<<<(NN + TB - 1) / TB, TB>>>(Z5, b5, out);
}